// round 7
// baseline (speedup 1.0000x reference)
#include <cuda_runtime.h>

// ComplexSuperposition: B=128, T=128, D=512 — fully fused.
// out_r[b,d] = sum_t real[b,t,d] * w[b,t]; out_i likewise.
// output_r[b,i,j] = out_r[b,i]*out_r[b,j] + out_i[b,i]*out_i[b,j]
// output_i[b,i,j] = out_i[b,i]*out_r[b,j] - out_r[b,i]*out_i[b,j]
// d_out: [output_r (128*512*512 f32)][output_i (...)]
//
// One block per batch (128 blocks x 1024 threads, single wave).
// Phase 1: block-local weighted reduction into shared (no global scratch).
// Phase 2: streaming outer-product stores at the DRAM write roofline.

#define BB 128
#define TT 128
#define DD 512

__global__ void __launch_bounds__(1024) fused_k(const float* __restrict__ re,
                                                const float* __restrict__ im,
                                                const float* __restrict__ w,
                                                float* __restrict__ out) {
    __shared__ float4 sr[8][DD / 4];   // 16 KB: per-tg partials, row 0 becomes final out_r
    __shared__ float4 si[8][DD / 4];   // 16 KB
    __shared__ float  ws[TT];          // weights for this batch

    int b   = blockIdx.x;
    int tid = threadIdx.x;

    // ---- Phase 1: weighted reduction over T ----
    int j  = tid & 127;        // float4 column index over D (0..127)
    int tg = tid >> 7;         // T-split group (0..7), 16 t's each

    if (tid < TT) ws[tid] = w[b * TT + tid];
    __syncthreads();

    const float4* rp = (const float4*)re + (size_t)b * TT * (DD / 4) + j;
    const float4* ip = (const float4*)im + (size_t)b * TT * (DD / 4) + j;

    float4 ar = make_float4(0.f, 0.f, 0.f, 0.f);
    float4 ai = make_float4(0.f, 0.f, 0.f, 0.f);

    int t0 = tg * 16;
#pragma unroll
    for (int k = 0; k < 16; ++k) {
        int t = t0 + k;
        float  wt = ws[t];                           // warp-uniform LDS broadcast
        float4 r  = __ldg(rp + (size_t)t * (DD / 4));
        float4 m  = __ldg(ip + (size_t)t * (DD / 4));
        ar.x = fmaf(r.x, wt, ar.x);  ar.y = fmaf(r.y, wt, ar.y);
        ar.z = fmaf(r.z, wt, ar.z);  ar.w = fmaf(r.w, wt, ar.w);
        ai.x = fmaf(m.x, wt, ai.x);  ai.y = fmaf(m.y, wt, ai.y);
        ai.z = fmaf(m.z, wt, ai.z);  ai.w = fmaf(m.w, wt, ai.w);
    }
    sr[tg][j] = ar;
    si[tg][j] = ai;
    __syncthreads();

    // combine the 8 partials; final vectors live in sr[0][*], si[0][*]
    if (tid < 256) {
        int q = tid >> 7;        // 0 = real, 1 = imag
        int l = tid & 127;
        float4 acc = make_float4(0.f, 0.f, 0.f, 0.f);
#pragma unroll
        for (int k = 0; k < 8; ++k) {
            float4 v = q ? si[k][l] : sr[k][l];
            acc.x += v.x; acc.y += v.y; acc.z += v.z; acc.w += v.w;
        }
        if (q) si[0][l] = acc; else sr[0][l] = acc;
    }
    __syncthreads();

    // ---- Phase 2: outer products, streamed to DRAM ----
    const float* srf = (const float*)&sr[0][0];   // out_r[b, 0..511]
    const float* sif = (const float*)&si[0][0];   // out_i[b, 0..511]

    int j4 = tid & 127;        // float4 column
    int rg = tid >> 7;         // row group (0..7)

    float4 br = sr[0][j4];     // column vector, hoisted
    float4 bi = si[0][j4];

    float4* outr = (float4*)(out + (size_t)b * DD * DD) + j4;
    float4* outi = outr + (size_t)BB * DD * DD / 4;

#pragma unroll 8
    for (int k = 0; k < 64; ++k) {
        int r = k * 8 + rg;                  // block writes contiguous 8-row slabs
        float arw = srf[r];                  // warp-uniform broadcast
        float aiw = sif[r];
        float4 vr, vi;
        vr.x = fmaf(arw, br.x, aiw * bi.x);
        vr.y = fmaf(arw, br.y, aiw * bi.y);
        vr.z = fmaf(arw, br.z, aiw * bi.z);
        vr.w = fmaf(arw, br.w, aiw * bi.w);
        vi.x = fmaf(aiw, br.x, -arw * bi.x);
        vi.y = fmaf(aiw, br.y, -arw * bi.y);
        vi.z = fmaf(aiw, br.z, -arw * bi.z);
        vi.w = fmaf(aiw, br.w, -arw * bi.w);
        __stcs(&outr[(size_t)r * 128], vr);  // streaming: never re-read
        __stcs(&outi[(size_t)r * 128], vi);
    }
}

extern "C" void kernel_launch(void* const* d_in, const int* in_sizes, int n_in,
                              void* d_out, int out_size) {
    const float* re = (const float*)d_in[0];   // input_real [128,128,512]
    const float* im = (const float*)d_in[1];   // input_imag [128,128,512]
    const float* w  = (const float*)d_in[2];   // weight     [128,128]
    float* out = (float*)d_out;                // [2,128,512,512]

    fused_k<<<BB, 1024>>>(re, im, w, out);
}

// round 8
// speedup vs baseline: 1.0312x; 1.0312x over previous
#include <cuda_runtime.h>

// ComplexSuperposition: B=128, T=128, D=512
// Single kernel with intra-grid producer/consumer overlap:
//   blocks [0, 512): reducers — 4 per batch, weighted sum over T -> g_outr/g_outi
//   blocks [512, 4608): outer  — 32 per batch, spin on per-batch ready flag,
//                                then stream rank-1 outer products to DRAM.
// d_out: [output_r (128*512*512 f32)][output_i (...)]

#define BB 128
#define TT 128
#define DD 512
#define NRED (BB * 4)          // 512 reducer blocks
#define NOUT (BB * 32)         // 4096 outer blocks

__device__ float g_outr[BB * DD];
__device__ float g_outi[BB * DD];
__device__ int   g_ready[BB];

__global__ void zero_k() {
    g_ready[threadIdx.x] = 0;
}

__global__ void __launch_bounds__(256) main_k(const float* __restrict__ re,
                                              const float* __restrict__ im,
                                              const float* __restrict__ w,
                                              float* __restrict__ out) {
    __shared__ __align__(16) char smem_raw[8192];
    int bid = blockIdx.x;
    int tid = threadIdx.x;

    if (bid < NRED) {
        // ───────────────── reducer: 4 blocks per batch ─────────────────
        float4 (*sr)[32] = (float4(*)[32])(smem_raw);
        float4 (*si)[32] = (float4(*)[32])(smem_raw + 4096);

        int b     = bid >> 2;
        int chunk = bid & 3;          // 128-float chunk of D
        int j     = tid & 31;         // float4 lane
        int tg    = tid >> 5;         // T-split group (0..7), 16 t's each

        size_t base4 = ((size_t)b * TT * DD + chunk * 128 + j * 4) >> 2;
        const float4* rp = (const float4*)re + base4;
        const float4* ip = (const float4*)im + base4;
        const float*  wp = w + b * TT;

        float4 ar = make_float4(0.f, 0.f, 0.f, 0.f);
        float4 ai = make_float4(0.f, 0.f, 0.f, 0.f);

        int t0 = tg * 16;
#pragma unroll 16
        for (int k = 0; k < 16; ++k) {
            int t = t0 + k;
            float  wt = __ldg(wp + t);
            float4 r  = __ldg(rp + (size_t)t * (DD / 4));
            float4 m  = __ldg(ip + (size_t)t * (DD / 4));
            ar.x = fmaf(r.x, wt, ar.x);  ar.y = fmaf(r.y, wt, ar.y);
            ar.z = fmaf(r.z, wt, ar.z);  ar.w = fmaf(r.w, wt, ar.w);
            ai.x = fmaf(m.x, wt, ai.x);  ai.y = fmaf(m.y, wt, ai.y);
            ai.z = fmaf(m.z, wt, ai.z);  ai.w = fmaf(m.w, wt, ai.w);
        }
        sr[tg][j] = ar;
        si[tg][j] = ai;
        __syncthreads();

        if (tid < 64) {
            int q = tid >> 5;         // 0 = real, 1 = imag
            int l = tid & 31;
            float4 acc = make_float4(0.f, 0.f, 0.f, 0.f);
#pragma unroll
            for (int k = 0; k < 8; ++k) {
                float4 v = q ? si[k][l] : sr[k][l];
                acc.x += v.x; acc.y += v.y; acc.z += v.z; acc.w += v.w;
            }
            float4* dst = (float4*)(q ? g_outi : g_outr);
            dst[((size_t)b * DD + chunk * 128 + l * 4) >> 2] = acc;
        }
        // publish: stores -> fence (all threads) -> barrier -> release arrive
        __threadfence();
        __syncthreads();
        if (tid == 0) atomicAdd(&g_ready[b], 1);

    } else {
        // ───────────────── outer: 32 blocks per batch ─────────────────
        float4* sr4 = (float4*)(smem_raw);          // 2 KB: out_r[b,:]
        float4* si4 = (float4*)(smem_raw + 2048);   // 2 KB: out_i[b,:]

        int obid = bid - NRED;
        int b    = obid >> 5;
        int tile = obid & 31;

        // wait for this batch's 4 reducer arrivals
        if (tid == 0) {
            while (atomicAdd(&g_ready[b], 0) < 4) __nanosleep(64);
        }
        __syncthreads();
        __threadfence();   // acquire: order flag observation before data loads

        const float4* gr = (const float4*)(g_outr + b * DD);
        const float4* gi = (const float4*)(g_outi + b * DD);
        if (tid < 128) sr4[tid] = gr[tid];
        else           si4[tid - 128] = gi[tid - 128];
        __syncthreads();

        const float* srf = (const float*)sr4;
        const float* sif = (const float*)si4;

        int j4 = tid & 127;
        int ih = tid >> 7;

        float4 br = sr4[j4];
        float4 bi = si4[j4];

        float4* outr = (float4*)(out + (size_t)b * DD * DD)
                       + (size_t)(tile * 16) * 128 + j4;
        float4* outi = outr + (size_t)BB * DD * DD / 4;

#pragma unroll
        for (int k = 0; k < 8; ++k) {
            int row = k * 2 + ih;
            int i   = tile * 16 + row;
            float arw = srf[i];
            float aiw = sif[i];
            float4 vr, vi;
            vr.x = fmaf(arw, br.x, aiw * bi.x);
            vr.y = fmaf(arw, br.y, aiw * bi.y);
            vr.z = fmaf(arw, br.z, aiw * bi.z);
            vr.w = fmaf(arw, br.w, aiw * bi.w);
            vi.x = fmaf(aiw, br.x, -arw * bi.x);
            vi.y = fmaf(aiw, br.y, -arw * bi.y);
            vi.z = fmaf(aiw, br.z, -arw * bi.z);
            vi.w = fmaf(aiw, br.w, -arw * bi.w);
            __stcs(&outr[(size_t)row * 128], vr);
            __stcs(&outi[(size_t)row * 128], vi);
        }
    }
}

extern "C" void kernel_launch(void* const* d_in, const int* in_sizes, int n_in,
                              void* d_out, int out_size) {
    const float* re = (const float*)d_in[0];   // input_real [128,128,512]
    const float* im = (const float*)d_in[1];   // input_imag [128,128,512]
    const float* w  = (const float*)d_in[2];   // weight     [128,128]
    float* out = (float*)d_out;                // [2,128,512,512]

    zero_k<<<1, BB>>>();                       // reset ready flags (globals persist)
    main_k<<<NRED + NOUT, 256>>>(re, im, w, out);
}